// round 11
// baseline (speedup 1.0000x reference)
#include <cuda_runtime.h>
#include <cuda_bf16.h>
#include <math.h>

// ---------------- problem constants ----------------
#define STEPS 20000
#define NCOL  2048
#define NCOL4 (NCOL/4)      // 512
#define CH    40            // steps per chunk
#define NCH   (STEPS/CH)    // 500 chunks
#define NWORK (NCH * NCOL)  // 1,024,000 (scalar k_chunk threads)
#define NT4   (NCH * NCOL4) // 256,000 (float4 k_main threads)
#define NBINS 200000
#define HISTN (NBINS + 1)
#define GC    5             // k_chunk prefetch group (steps)
#define NGC   (CH / GC)     // 8
#define BG    10            // boundary prefetch group (chunks)
#define NBG   (NCH / BG)    // 50
#define NGM   (CH / 2)      // 20 k_main groups of 2 steps

#define R1_SUM_D 123020000.0
__device__ __constant__ float c_invr[4] = {
    1.0f / 1.0e6f, (float)(1.0 / R1_SUM_D), 1.0f / 1.0e5f, (float)(1.0 / 0.2)
};

__device__ __forceinline__ void get_thresholds(float& A, float& B, float& C) {
    const double c0 = 50000000.0 / R1_SUM_D;
    const double c2 = c0 + 3000000.0 / R1_SUM_D;
    const double c3 = c2 + 20000.0 / R1_SUM_D;
    A = (float)c0; B = (float)c2; C = (float)c3;
}

// ---- pinned (un-sinkable) loads ----
__device__ __forceinline__ float vldg_f32(const float* p) {
    float v; asm volatile("ld.global.nc.f32 %0, [%1];" : "=f"(v) : "l"(p)); return v;
}
__device__ __forceinline__ float4 vldg_f4(const float4* p) {
    float4 v;
    asm volatile("ld.global.nc.v4.f32 {%0,%1,%2,%3}, [%4];"
                 : "=f"(v.x), "=f"(v.y), "=f"(v.z), "=f"(v.w) : "l"(p));
    return v;
}
__device__ __forceinline__ unsigned vldg_u32(const unsigned* p) {
    unsigned v; asm volatile("ld.global.nc.u32 %0, [%1];" : "=r"(v) : "l"(p)); return v;
}

// ---------------- device scratch ----------------
__device__ float4        g_dwl[NWORK];                  // {dA,dB,dC,dD}
__device__ unsigned      g_maps[NWORK];
__device__ unsigned char g_entry[NWORK];
__device__ float         g_offs[NWORK];
__device__ unsigned char g_state[(size_t)STEPS * NCOL]; // 4x 2-bit entry-indexed states
__device__ int           g_hist[HISTN];

__device__ __forceinline__ int f1_of(float u, float A, float B, float C) {
    return (u < A) ? 0 : ((u < B) ? 2 : ((u < C) ? 3 : 0));
}
__device__ __forceinline__ int advance(int s, int f1) {
    return (s == 0) ? 1 : ((s == 1) ? f1 : 0);
}
__device__ __forceinline__ float invr_of(int s) {
    return (s == 0) ? c_invr[0] : ((s == 1) ? c_invr[1] : ((s == 2) ? c_invr[2] : c_invr[3]));
}

// smallest j in [0,NBINS] with (float)j*0.002f >= t  (branchless +-2 correction)
__device__ __forceinline__ int bucket_arith(float t) {
    int j = (int)ceilf(t * 500.0f);
    j = max(0, min(j, NBINS));
    j += (j < NBINS) && ((float)j * 0.002f < t);
    j += (j < NBINS) && ((float)j * 0.002f < t);
    j -= (j > 0) && ((float)(j - 1) * 0.002f >= t);
    j -= (j > 0) && ((float)(j - 1) * 0.002f >= t);
    return j;
}

// ---------------- K0: zero histogram ----------------
__global__ void k_zero() {
    int i = blockIdx.x * blockDim.x + threadIdx.x;
    if (i < HISTN) g_hist[i] = 0;
}

// ---------------- K1: chunk maps + dwell totals + packed per-step states ----------------
__global__ void __launch_bounds__(256) k_chunk(const float* __restrict__ ucat,
                                               const float* __restrict__ uexp) {
    int gid = blockIdx.x * blockDim.x + threadIdx.x;
    int col = gid & (NCOL - 1);
    int c   = gid >> 11;
    float A, B, C; get_thresholds(A, B, C);

    const float* pc = ucat + (size_t)c * CH * NCOL + col;
    const float* pe = uexp + (size_t)c * CH * NCOL + col;
    unsigned char* ps = g_state + (size_t)c * CH * NCOL + col;

    int   sA = 0, sB = 1, sC = 0;
    float aA = 0.f, aB = 0.f, aT = 0.f, g0 = 0.f;

    float b1[2][GC], b2[2][GC];
    #pragma unroll
    for (int jj = 0; jj < GC; jj++) {
        b1[0][jj] = vldg_f32(pc + (size_t)jj * NCOL);
        b2[0][jj] = vldg_f32(pe + (size_t)jj * NCOL);
    }

    #pragma unroll
    for (int g = 0; g < NGC; g++) {
        const int cur = g & 1, nxt = cur ^ 1;
        if (g + 1 < NGC) {
            #pragma unroll
            for (int jj = 0; jj < GC; jj++) {
                b1[nxt][jj] = vldg_f32(pc + (size_t)((g + 1) * GC + jj) * NCOL);
                b2[nxt][jj] = vldg_f32(pe + (size_t)((g + 1) * GC + jj) * NCOL);
            }
        }
        #pragma unroll
        for (int jj = 0; jj < GC; jj++) {
            const int k = g * GC + jj;
            float u1 = b1[cur][jj];
            float u2 = b2[cur][jj];
            float gg = -__logf(1.0f - u2);
            int   f  = f1_of(u1, A, B, C);
            if (k == 0) {
                ps[0] = (unsigned char)0xE4;     // identity map: entry e -> state e
                g0 = gg;
                aA = gg * c_invr[0];
                aB = gg * c_invr[1];
                sA = 1; sB = f; sC = 0;
            } else {
                ps[(size_t)k * NCOL] =
                    (unsigned char)(sA | (sB << 2) | (sC << 4) | (sC << 6));
                aT = fmaf(gg, invr_of(sC), aT);
                aA = fmaf(gg, invr_of(sA), aA);
                aB = fmaf(gg, invr_of(sB), aB);
                sC = advance(sC, f);
                sA = advance(sA, f);
                sB = advance(sB, f);
            }
        }
    }

    float4 d;
    d.x = aA;
    d.y = aB;
    d.z = fmaf(g0, c_invr[2], aT);
    d.w = fmaf(g0, c_invr[3], aT);
    g_dwl[gid]  = d;
    g_maps[gid] = (unsigned)sA | ((unsigned)sB << 8) | ((unsigned)sC << 16);
}

// ---------------- K2: per-column scan over chunks (named-buffer ping-pong) ----------------
__global__ void __launch_bounds__(256) k_boundary() {
    int col = blockIdx.x * blockDim.x + threadIdx.x;   // 0..2047
    int s = 0;
    double t = 0.0;

    float4   bdA[BG], bdB[BG];
    unsigned bmA[BG], bmB[BG];
    #pragma unroll
    for (int jj = 0; jj < BG; jj++) {
        bdA[jj] = vldg_f4(&g_dwl[jj * NCOL + col]);
        bmA[jj] = vldg_u32(&g_maps[jj * NCOL + col]);
    }

    for (int g = 0; g < NBG; g += 2) {
        if (g + 1 < NBG) {
            #pragma unroll
            for (int jj = 0; jj < BG; jj++) {
                bdB[jj] = vldg_f4(&g_dwl[((g + 1) * BG + jj) * NCOL + col]);
                bmB[jj] = vldg_u32(&g_maps[((g + 1) * BG + jj) * NCOL + col]);
            }
        }
        #pragma unroll
        for (int jj = 0; jj < BG; jj++) {
            int idx = (g * BG + jj) * NCOL + col;
            g_entry[idx] = (unsigned char)s;
            g_offs[idx]  = (float)t;
            float4 d = bdA[jj];
            float dv = (s == 0) ? d.x : (s == 1) ? d.y : (s == 2) ? d.z : d.w;
            t += (double)dv;
            unsigned m = bmA[jj];
            int sh = (s < 2) ? s : 2;
            s = (int)((m >> (8 * sh)) & 3u);
        }
        if (g + 2 < NBG) {
            #pragma unroll
            for (int jj = 0; jj < BG; jj++) {
                bdA[jj] = vldg_f4(&g_dwl[((g + 2) * BG + jj) * NCOL + col]);
                bmA[jj] = vldg_u32(&g_maps[((g + 2) * BG + jj) * NCOL + col]);
            }
        }
        #pragma unroll
        for (int jj = 0; jj < BG; jj++) {
            int idx = ((g + 1) * BG + jj) * NCOL + col;
            g_entry[idx] = (unsigned char)s;
            g_offs[idx]  = (float)t;
            float4 d = bdB[jj];
            float dv = (s == 0) ? d.x : (s == 1) ? d.y : (s == 2) ? d.z : d.w;
            t += (double)dv;
            unsigned m = bmB[jj];
            int sh = (s < 2) ? s : 2;
            s = (int)((m >> (8 * sh)) & 3u);
        }
    }
}

// ---------------- K3: final resolve (4 cols/thread, float4) ----------------
#define DO_COL(uu, sw, jc, pvv, tvv) {                                   \
    int s = ((sw) >> sht[jc]) & 3;                                       \
    float gg = -__logf(1.0f - (uu));                                     \
    float ir = (s == 0) ? IR0 : ((s == 1) ? IR1 : ((s == 2) ? IR2 : IR3)); \
    t[jc] += gg * ir;                                                    \
    bool ph = (s == 0);                                                  \
    pvv = ph ? 1.0f : 0.0f;  tvv = t[jc];                                \
    if (ph) {                                                            \
        if (t[jc] > edge[jc]) {                                          \
            if (rc[jc]) atomicAdd(&g_hist[jb[jc]], rc[jc]);              \
            jb[jc] = bucket_arith(t[jc]);                                \
            edge[jc] = (float)jb[jc] * 0.002f; rc[jc] = 1;               \
        } else rc[jc]++;                                                 \
    } else nz++; }

#define PROC_STEP(u4, sw, k) {                        \
    float4 pv, tv;                                     \
    DO_COL((u4).x, (sw), 0, pv.x, tv.x);               \
    DO_COL((u4).y, (sw), 1, pv.y, tv.y);               \
    DO_COL((u4).z, (sw), 2, pv.z, tv.z);               \
    DO_COL((u4).w, (sw), 3, pv.w, tv.w);               \
    __stcs(pp + (size_t)(k) * NCOL4, pv);              \
    __stcs(pt + (size_t)(k) * NCOL4, tv); }

__global__ void __launch_bounds__(256) k_main(const float* __restrict__ uexp,
                                              float* __restrict__ phot,
                                              float* __restrict__ cum) {
    int gid  = blockIdx.x * blockDim.x + threadIdx.x;  // 0 .. NT4-1
    int col4 = gid & (NCOL4 - 1);
    int c    = gid >> 9;

    size_t rowbase = (size_t)c * CH * NCOL + 4 * col4;
    const float4*   pe = (const float4*)(uexp + rowbase);
    const unsigned* ps = (const unsigned*)(g_state + rowbase);
    float4* pp = (float4*)(phot + rowbase);
    float4* pt = (float4*)(cum  + rowbase);

    const float IR0 = c_invr[0], IR1 = c_invr[1], IR2 = c_invr[2], IR3 = c_invr[3];

    int idx0 = c * NCOL + 4 * col4;
    uchar4 e4 = *(const uchar4*)&g_entry[idx0];
    float4 o4 = *(const float4*)&g_offs[idx0];

    int   sht[4]  = {0 + 2 * e4.x, 8 + 2 * e4.y, 16 + 2 * e4.z, 24 + 2 * e4.w};
    float t[4]    = {o4.x, o4.y, o4.z, o4.w};
    int   jb[4];  float edge[4];  int rc[4];
    #pragma unroll
    for (int jc = 0; jc < 4; jc++) {
        jb[jc] = bucket_arith(t[jc]);
        edge[jc] = (float)jb[jc] * 0.002f;
        rc[jc] = 0;
    }
    int nz = 0;

    float4   ueA[2], ueB[2];
    unsigned suA[2], suB[2];
    #pragma unroll
    for (int jj = 0; jj < 2; jj++) {
        ueA[jj] = vldg_f4(pe + (size_t)jj * NCOL4);
        suA[jj] = vldg_u32(ps + (size_t)jj * NCOL4);
    }

    for (int g = 0; g < NGM; g += 2) {
        if (g + 1 < NGM) {
            #pragma unroll
            for (int jj = 0; jj < 2; jj++) {
                ueB[jj] = vldg_f4(pe + (size_t)((g + 1) * 2 + jj) * NCOL4);
                suB[jj] = vldg_u32(ps + (size_t)((g + 1) * 2 + jj) * NCOL4);
            }
        }
        PROC_STEP(ueA[0], suA[0], g * 2 + 0);
        PROC_STEP(ueA[1], suA[1], g * 2 + 1);
        if (g + 2 < NGM) {
            #pragma unroll
            for (int jj = 0; jj < 2; jj++) {
                ueA[jj] = vldg_f4(pe + (size_t)((g + 2) * 2 + jj) * NCOL4);
                suA[jj] = vldg_u32(ps + (size_t)((g + 2) * 2 + jj) * NCOL4);
            }
        }
        PROC_STEP(ueB[0], suB[0], (g + 1) * 2 + 0);
        PROC_STEP(ueB[1], suB[1], (g + 1) * 2 + 1);
    }

    #pragma unroll
    for (int jc = 0; jc < 4; jc++)
        if (rc[jc]) atomicAdd(&g_hist[jb[jc]], rc[jc]);

    int tot = __reduce_add_sync(0xffffffffu, nz);
    if ((threadIdx.x & 31) == 0 && tot) atomicAdd(&g_hist[0], tot);
}

// ---------------- K4: int hist -> float32 output tail ----------------
__global__ void k_hist_out(float* __restrict__ out_hist) {
    int i = blockIdx.x * blockDim.x + threadIdx.x;
    if (i < HISTN) out_hist[i] = (float)g_hist[i];
}

// ---------------- launch ----------------
extern "C" void kernel_launch(void* const* d_in, const int* in_sizes, int n_in,
                              void* d_out, int out_size) {
    const float* ucat = (const float*)d_in[0];
    const float* uexp = (const float*)d_in[1];
    float* out = (float*)d_out;

    const size_t n_elem = (size_t)STEPS * NCOL;
    float* out_phot = out;
    float* out_cum  = out + n_elem;
    float* out_hist = out + 2 * n_elem;

    const int th = 256;
    const int hist_blocks = (HISTN + th - 1) / th;

    k_zero<<<hist_blocks, th>>>();
    k_chunk<<<NWORK / th, th>>>(ucat, uexp);          // 4000 blocks
    k_boundary<<<NCOL / th, th>>>();                  // 8 blocks
    k_main<<<NT4 / th, th>>>(uexp, out_phot, out_cum); // 1000 blocks
    k_hist_out<<<hist_blocks, th>>>(out_hist);
}

// round 12
// speedup vs baseline: 1.5803x; 1.5803x over previous
#include <cuda_runtime.h>
#include <cuda_bf16.h>
#include <math.h>

// ---------------- problem constants ----------------
#define STEPS 20000
#define NCOL  2048
#define CH    100           // steps per chunk
#define NCH   (STEPS/CH)    // 200 chunks
#define NWORK (NCH * NCOL)
#define NBINS 200000
#define HISTN (NBINS + 1)
#define NST   (CH/4)        // 25 four-step stages per chunk
#define DEPC  4             // k_chunk cp.async pipeline depth (stages)
#define DEPM  6             // k_main  cp.async pipeline depth (stages)
#define CPB   (NCOL/256)    // 8 col-groups (blocks) per chunk
#define BG    10            // boundary prefetch group (chunks)
#define NBG   (NCH/BG)      // 20

#define R1_SUM_D 123020000.0
__device__ __constant__ float c_invr[4] = {
    1.0f / 1.0e6f, (float)(1.0 / R1_SUM_D), 1.0f / 1.0e5f, (float)(1.0 / 0.2)
};

__device__ __forceinline__ void get_thresholds(float& A, float& B, float& C) {
    const double c0 = 50000000.0 / R1_SUM_D;
    const double c2 = c0 + 3000000.0 / R1_SUM_D;
    const double c3 = c2 + 20000.0 / R1_SUM_D;
    A = (float)c0; B = (float)c2; C = (float)c3;
}

// ---- cp.async helpers (no scoreboard: deep async pipelines) ----
__device__ __forceinline__ void cpa4(unsigned smem, const void* g) {
    asm volatile("cp.async.ca.shared.global [%0], [%1], 4;" :: "r"(smem), "l"(g));
}
__device__ __forceinline__ void cpa_commit() {
    asm volatile("cp.async.commit_group;" ::: "memory");
}
template <int N>
__device__ __forceinline__ void cpa_wait() {
    asm volatile("cp.async.wait_group %0;" :: "n"(N) : "memory");
}

// ---- pinned loads (for boundary scan) ----
__device__ __forceinline__ float4 vldg_f4(const float4* p) {
    float4 v;
    asm volatile("ld.global.nc.v4.f32 {%0,%1,%2,%3}, [%4];"
                 : "=f"(v.x), "=f"(v.y), "=f"(v.z), "=f"(v.w) : "l"(p));
    return v;
}
__device__ __forceinline__ unsigned vldg_u32(const unsigned* p) {
    unsigned v; asm volatile("ld.global.nc.u32 %0, [%1];" : "=r"(v) : "l"(p)); return v;
}

// ---------------- device scratch ----------------
__device__ float4        g_dwl[NWORK];                 // {dA,dB,dC,dD}
__device__ unsigned      g_maps[NWORK];
__device__ unsigned char g_entry[NWORK];
__device__ float         g_offs[NWORK];
__device__ unsigned      g_state4[(size_t)(STEPS/4) * NCOL]; // 4 step-bytes per word
__device__ int           g_hist[HISTN];

__device__ __forceinline__ int f1_of(float u, float A, float B, float C) {
    return (u < A) ? 0 : ((u < B) ? 2 : ((u < C) ? 3 : 0));
}
__device__ __forceinline__ int advance(int s, int f1) {
    return (s == 0) ? 1 : ((s == 1) ? f1 : 0);
}
__device__ __forceinline__ float invr_of(int s) {
    return (s == 0) ? c_invr[0] : ((s == 1) ? c_invr[1] : ((s == 2) ? c_invr[2] : c_invr[3]));
}

// smallest j in [0,NBINS] with (float)j*0.002f >= t (branchless +-2 correction)
__device__ __forceinline__ int bucket_arith(float t) {
    int j = (int)ceilf(t * 500.0f);
    j = max(0, min(j, NBINS));
    j += (j < NBINS) && ((float)j * 0.002f < t);
    j += (j < NBINS) && ((float)j * 0.002f < t);
    j -= (j > 0) && ((float)(j - 1) * 0.002f >= t);
    j -= (j > 0) && ((float)(j - 1) * 0.002f >= t);
    return j;
}

// ---------------- K0: zero histogram ----------------
__global__ void k_zero() {
    int i = blockIdx.x * blockDim.x + threadIdx.x;
    if (i < HISTN) g_hist[i] = 0;
}

// ---------------- K1: chunk maps + dwell totals + packed states (cp.async) ----------------
__global__ void __launch_bounds__(256) k_chunk(const float* __restrict__ ucat,
                                               const float* __restrict__ uexp) {
    __shared__ float s_uc[DEPC][4][256];
    __shared__ float s_ue[DEPC][4][256];

    int tid = threadIdx.x;
    int c   = blockIdx.x >> 3;          // chunk
    int cg  = blockIdx.x & 7;           // col group
    int col = cg * 256 + tid;
    float A, B, C; get_thresholds(A, B, C);

    const float* pc = ucat + (size_t)c * CH * NCOL + col;
    const float* pe = uexp + (size_t)c * CH * NCOL + col;

    unsigned uc_s = (unsigned)__cvta_generic_to_shared(&s_uc[0][0][tid]);
    unsigned ue_s = (unsigned)__cvta_generic_to_shared(&s_ue[0][0][tid]);
    const unsigned STG_B = 4 * 256 * 4;      // bytes per stage buffer
    const unsigned ROW_B = 256 * 4;

    // prologue: fill DEPC stages
    #pragma unroll
    for (int s = 0; s < DEPC; s++) {
        #pragma unroll
        for (int j = 0; j < 4; j++) {
            cpa4(uc_s + s * STG_B + j * ROW_B, pc + (size_t)(4 * s + j) * NCOL);
            cpa4(ue_s + s * STG_B + j * ROW_B, pe + (size_t)(4 * s + j) * NCOL);
        }
        cpa_commit();
    }

    int   sA = 0, sB = 1, sC = 0;
    float aA = 0.f, aB = 0.f, aT = 0.f, g0 = 0.f;

    for (int s = 0; s < NST; s++) {
        if (s < NST - DEPC)       cpa_wait<DEPC - 1>();
        else if (s == NST - DEPC) cpa_wait<0>();
        int buf = s % DEPC;

        unsigned stword = 0;
        #pragma unroll
        for (int j = 0; j < 4; j++) {
            const int k = 4 * s + j;
            float u1 = s_uc[buf][j][tid];
            float u2 = s_ue[buf][j][tid];
            float gg = -__logf(1.0f - u2);
            int   f  = f1_of(u1, A, B, C);
            if (k == 0) {
                stword |= 0xE4u;                 // identity: entry e -> state e
                g0 = gg;
                aA = gg * c_invr[0];
                aB = gg * c_invr[1];
                sA = 1; sB = f; sC = 0;
            } else {
                unsigned b = (unsigned)(sA | (sB << 2) | (sC << 4) | (sC << 6));
                stword |= b << (8 * j);
                aT = fmaf(gg, invr_of(sC), aT);
                aA = fmaf(gg, invr_of(sA), aA);
                aB = fmaf(gg, invr_of(sB), aB);
                sC = advance(sC, f);
                sA = advance(sA, f);
                sB = advance(sB, f);
            }
        }
        g_state4[(size_t)(c * NST + s) * NCOL + col] = stword;

        if (s + DEPC < NST) {
            int nb = (s + DEPC) % DEPC;
            #pragma unroll
            for (int j = 0; j < 4; j++) {
                cpa4(uc_s + nb * STG_B + j * ROW_B, pc + (size_t)(4 * (s + DEPC) + j) * NCOL);
                cpa4(ue_s + nb * STG_B + j * ROW_B, pe + (size_t)(4 * (s + DEPC) + j) * NCOL);
            }
            cpa_commit();
        }
    }

    int gidx = c * NCOL + col;
    float4 d;
    d.x = aA;
    d.y = aB;
    d.z = fmaf(g0, c_invr[2], aT);
    d.w = fmaf(g0, c_invr[3], aT);
    g_dwl[gidx]  = d;
    g_maps[gidx] = (unsigned)sA | ((unsigned)sB << 8) | ((unsigned)sC << 16);
}

// ---------------- K2: per-column scan over chunks (named-buffer ping-pong) ----------------
__global__ void __launch_bounds__(256) k_boundary() {
    int col = blockIdx.x * blockDim.x + threadIdx.x;   // 0..2047
    int s = 0;
    double t = 0.0;

    float4   bdA[BG], bdB[BG];
    unsigned bmA[BG], bmB[BG];
    #pragma unroll
    for (int jj = 0; jj < BG; jj++) {
        bdA[jj] = vldg_f4(&g_dwl[jj * NCOL + col]);
        bmA[jj] = vldg_u32(&g_maps[jj * NCOL + col]);
    }

    for (int g = 0; g < NBG; g += 2) {
        if (g + 1 < NBG) {
            #pragma unroll
            for (int jj = 0; jj < BG; jj++) {
                bdB[jj] = vldg_f4(&g_dwl[((g + 1) * BG + jj) * NCOL + col]);
                bmB[jj] = vldg_u32(&g_maps[((g + 1) * BG + jj) * NCOL + col]);
            }
        }
        #pragma unroll
        for (int jj = 0; jj < BG; jj++) {
            int idx = (g * BG + jj) * NCOL + col;
            g_entry[idx] = (unsigned char)s;
            g_offs[idx]  = (float)t;
            float4 d = bdA[jj];
            float dv = (s == 0) ? d.x : (s == 1) ? d.y : (s == 2) ? d.z : d.w;
            t += (double)dv;
            unsigned m = bmA[jj];
            int sh = (s < 2) ? s : 2;
            s = (int)((m >> (8 * sh)) & 3u);
        }
        if (g + 2 < NBG) {
            #pragma unroll
            for (int jj = 0; jj < BG; jj++) {
                bdA[jj] = vldg_f4(&g_dwl[((g + 2) * BG + jj) * NCOL + col]);
                bmA[jj] = vldg_u32(&g_maps[((g + 2) * BG + jj) * NCOL + col]);
            }
        }
        #pragma unroll
        for (int jj = 0; jj < BG; jj++) {
            int idx = ((g + 1) * BG + jj) * NCOL + col;
            g_entry[idx] = (unsigned char)s;
            g_offs[idx]  = (float)t;
            float4 d = bdB[jj];
            float dv = (s == 0) ? d.x : (s == 1) ? d.y : (s == 2) ? d.z : d.w;
            t += (double)dv;
            unsigned m = bmB[jj];
            int sh = (s < 2) ? s : 2;
            s = (int)((m >> (8 * sh)) & 3u);
        }
    }
}

// ---------------- K3: final resolve (cp.async staged) ----------------
__global__ void __launch_bounds__(256) k_main(const float* __restrict__ uexp,
                                              float* __restrict__ phot,
                                              float* __restrict__ cum) {
    __shared__ float    s_ue[DEPM][4][256];
    __shared__ unsigned s_st[DEPM][256];

    int tid = threadIdx.x;
    int c   = blockIdx.x >> 3;
    int cg  = blockIdx.x & 7;
    int col = cg * 256 + tid;

    const float*    pe = uexp + (size_t)c * CH * NCOL + col;
    const unsigned* pw = g_state4 + (size_t)c * NST * NCOL + col;
    float* pp = phot + (size_t)c * CH * NCOL + col;
    float* pt = cum  + (size_t)c * CH * NCOL + col;

    unsigned ue_s = (unsigned)__cvta_generic_to_shared(&s_ue[0][0][tid]);
    unsigned st_s = (unsigned)__cvta_generic_to_shared(&s_st[0][tid]);
    const unsigned STG_B = 4 * 256 * 4;
    const unsigned ROW_B = 256 * 4;

    #pragma unroll
    for (int s = 0; s < DEPM; s++) {
        #pragma unroll
        for (int j = 0; j < 4; j++)
            cpa4(ue_s + s * STG_B + j * ROW_B, pe + (size_t)(4 * s + j) * NCOL);
        cpa4(st_s + s * ROW_B, pw + (size_t)s * NCOL);
        cpa_commit();
    }

    int gidx = c * NCOL + col;
    int   e   = (int)g_entry[gidx];
    float t   = g_offs[gidx];
    int   sht = 2 * e;

    int   jb = bucket_arith(t);
    float edge = (float)jb * 0.002f;
    int   rc = 0, nz = 0;

    const float IR0 = c_invr[0], IR1 = c_invr[1], IR2 = c_invr[2], IR3 = c_invr[3];

    for (int s = 0; s < NST; s++) {
        if (s < NST - DEPM)       cpa_wait<DEPM - 1>();
        else if (s == NST - DEPM) cpa_wait<0>();
        int buf = s % DEPM;
        unsigned w = s_st[buf][tid];

        #pragma unroll
        for (int j = 0; j < 4; j++) {
            const int k = 4 * s + j;
            float u2 = s_ue[buf][j][tid];
            int   st = (int)((w >> (8 * j + sht)) & 3u);
            float gg = -__logf(1.0f - u2);
            float ir = (st == 0) ? IR0 : ((st == 1) ? IR1 : ((st == 2) ? IR2 : IR3));
            t += gg * ir;
            bool ph = (st == 0);
            __stcs(pp + (size_t)k * NCOL, ph ? 1.0f : 0.0f);
            __stcs(pt + (size_t)k * NCOL, t);
            if (ph) {
                if (t > edge) {                  // rare: bin crossing
                    if (rc) atomicAdd(&g_hist[jb], rc);
                    jb = bucket_arith(t); edge = (float)jb * 0.002f; rc = 1;
                } else rc++;
            } else nz++;
        }

        if (s + DEPM < NST) {
            int nb = (s + DEPM) % DEPM;
            #pragma unroll
            for (int j = 0; j < 4; j++)
                cpa4(ue_s + nb * STG_B + j * ROW_B, pe + (size_t)(4 * (s + DEPM) + j) * NCOL);
            cpa4(st_s + nb * ROW_B, pw + (size_t)(s + DEPM) * NCOL);
            cpa_commit();
        }
    }
    if (rc) atomicAdd(&g_hist[jb], rc);

    int tot = __reduce_add_sync(0xffffffffu, nz);
    if ((threadIdx.x & 31) == 0 && tot) atomicAdd(&g_hist[0], tot);
}

// ---------------- K4: int hist -> float32 output tail ----------------
__global__ void k_hist_out(float* __restrict__ out_hist) {
    int i = blockIdx.x * blockDim.x + threadIdx.x;
    if (i < HISTN) out_hist[i] = (float)g_hist[i];
}

// ---------------- launch ----------------
extern "C" void kernel_launch(void* const* d_in, const int* in_sizes, int n_in,
                              void* d_out, int out_size) {
    const float* ucat = (const float*)d_in[0];
    const float* uexp = (const float*)d_in[1];
    float* out = (float*)d_out;

    const size_t n_elem = (size_t)STEPS * NCOL;
    float* out_phot = out;
    float* out_cum  = out + n_elem;
    float* out_hist = out + 2 * n_elem;

    const int th = 256;
    const int hist_blocks = (HISTN + th - 1) / th;
    const int work_blocks = NCH * CPB;            // 1600

    k_zero<<<hist_blocks, th>>>();
    k_chunk<<<work_blocks, th>>>(ucat, uexp);
    k_boundary<<<NCOL / th, th>>>();
    k_main<<<work_blocks, th>>>(uexp, out_phot, out_cum);
    k_hist_out<<<hist_blocks, th>>>(out_hist);
}